// round 1
// baseline (speedup 1.0000x reference)
#include <cuda_runtime.h>
#include <cuda_bf16.h>

// Problem shape (fixed by reference)
#define BATCH 4096
#define SLOTS 26
#define MAX_NNZ 10
#define EMB 64
#define NUM_SLOTS (BATCH * SLOTS)          // 106496 (b,s) pairs
#define LANES_PER_SLOT 16                  // each lane owns a float4 (16 floats4 * 4 = 64 floats)

__global__ __launch_bounds__(256) void emb_combine_kernel(
    const int* __restrict__ keys,    // [B, S, N]
    const int* __restrict__ mask,    // [B, S, N]  (bool serialized as int32; nonzero = valid)
    const float* __restrict__ table, // [VOCAB, EMB]
    float* __restrict__ out)         // [B, S, EMB]
{
    int gtid = blockIdx.x * blockDim.x + threadIdx.x;
    int slot = gtid >> 4;            // 16 threads per (b,s)
    int lane = gtid & 15;            // which float4 of the row
    if (slot >= NUM_SLOTS) return;

    const int base = slot * MAX_NNZ;

    float4 acc = make_float4(0.f, 0.f, 0.f, 0.f);
    int cnt = 0;

#pragma unroll
    for (int j = 0; j < MAX_NNZ; j++) {
        int m = __ldg(&mask[base + j]);
        int k = __ldg(&keys[base + j]);
        if (m) {
            const float4* row = reinterpret_cast<const float4*>(table + (size_t)k * EMB);
            float4 v = __ldg(&row[lane]);
            acc.x += v.x; acc.y += v.y; acc.z += v.z; acc.w += v.w;
            cnt++;
        }
    }

    // mean combiner: divide by max(count, 1)
    float inv = 1.0f / (float)(cnt > 0 ? cnt : 1);
    acc.x *= inv; acc.y *= inv; acc.z *= inv; acc.w *= inv;

    reinterpret_cast<float4*>(out + (size_t)slot * EMB)[lane] = acc;
}

extern "C" void kernel_launch(void* const* d_in, const int* in_sizes, int n_in,
                              void* d_out, int out_size) {
    const int*   keys  = (const int*)d_in[0];
    const int*   mask  = (const int*)d_in[1];
    const float* table = (const float*)d_in[2];
    float*       out   = (float*)d_out;

    const int total_threads = NUM_SLOTS * LANES_PER_SLOT;  // 1,703,936
    const int block = 256;
    const int grid = (total_threads + block - 1) / block;
    emb_combine_kernel<<<grid, block>>>(keys, mask, table, out);
}